// round 10
// baseline (speedup 1.0000x reference)
#include <cuda_runtime.h>
#include <cuda_bf16.h>
#include <math.h>
#include <stdint.h>

#define BATCH 16384
#define TT 32
#define SS 16
#define NROWS_B (BATCH*TT)   // 524288
#define NROWS_0 (BATCH*SS)   // 262144
#define NB_BLOCKS (NROWS_B/128)  // 4096
#define N0_BLOCKS (NROWS_0/128)  // 2048

// ---------------- scratch (device globals; no allocations allowed) -------------
__device__ float g_qkvb[(size_t)NROWS_B*256];   // q(128)|v(128) of clin(beta)
__device__ float g_qkv0[(size_t)NROWS_0*384];   // clin(mem0): q|k|v
__device__ float g_alpha[NROWS_B];
__device__ float g_ptrs[(size_t)NROWS_B*16];
__device__ float g_betaT[(size_t)BATCH*128];    // beta at t=31 (for mem_f)
__device__ unsigned short g_Wt_hi[384*128];     // W^T split hi (bf16 bits): row n, col d
__device__ unsigned short g_Wt_lo[384*128];
__device__ float g_ropeC[1024], g_ropeS[1024];  // [t][f] rope tables
__device__ int   g_active;

__device__ __forceinline__ uint32_t smem_u32(const void* p) {
    uint32_t a;
    asm("{ .reg .u64 t; cvta.to.shared.u64 t, %1; cvt.u32.u64 %0, t; }" : "=r"(a) : "l"(p));
    return a;
}

#define LDSM4(r, a) \
    asm volatile("ldmatrix.sync.aligned.m8n8.x4.shared.b16 {%0,%1,%2,%3}, [%4];" \
        : "=r"((r)[0]), "=r"((r)[1]), "=r"((r)[2]), "=r"((r)[3]) : "r"(a))

// ---------------- build combined transposed/split weight -----------------------
__global__ void build_wt_kernel(const float* __restrict__ Wqr, const float* __restrict__ Wqi,
                                const float* __restrict__ Wkr, const float* __restrict__ Wki,
                                const float* __restrict__ Wvr, const float* __restrict__ Wvi) {
    int idx = blockIdx.x * blockDim.x + threadIdx.x;
    if (idx >= 384*128) return;
    int n = idx / 128, d = idx % 128;          // n = output col, d = input dim
    int grp = n >> 7, cc = n & 127, e = cc & 63, im = cc >> 6;
    const float* Wr = (grp == 0) ? Wqr : (grp == 1) ? Wkr : Wvr;
    const float* Wi = (grp == 0) ? Wqi : (grp == 1) ? Wki : Wvi;
    int dr = d & 63;
    float v;
    if (im == 0) v = (d < 64) ? Wr[e*64 + dr] : -Wi[e*64 + dr];
    else         v = (d < 64) ? Wi[e*64 + dr] :  Wr[e*64 + dr];
    __nv_bfloat16 h = __float2bfloat16(v);
    float lo = v - __bfloat162float(h);
    __nv_bfloat16 l = __float2bfloat16(lo);
    g_Wt_hi[idx] = __bfloat16_as_ushort(h);
    g_Wt_lo[idx] = __bfloat16_as_ushort(l);
}

__global__ void rope_kernel() {
    int idx = blockIdx.x * blockDim.x + threadIdx.x;
    if (idx >= 1024) return;
    int t = idx >> 5, f = idx & 31;
    double freq = pow(10000.0, -((double)(2*f)) / 64.0);
    float ang = (float)((double)t * freq);
    g_ropeC[idx] = cosf(ang);
    g_ropeS[idx] = sinf(ang);
}

__global__ void reset_kernel() { g_active = 0; }

// ---------------- slim prep: alpha + ptr recurrences (16 lanes / batch) --------
__global__ __launch_bounds__(256) void ptr_alpha_kernel(const float* __restrict__ ctrl,
                                                        const float* __restrict__ ptr0) {
    const int grp = threadIdx.x >> 4;          // 0..15: batch within block
    const int s = threadIdx.x & 15;
    const int b = blockIdx.x*16 + grp;
    float p = ptr0[b*16 + s];
    float alpha = 1.f;
    const float* cb = ctrl + (size_t)b*96;
    for (int t = 0; t < TT; ++t) {
        float c0 = cb[t*3 + 0], c1 = cb[t*3 + 1], c2 = cb[t*3 + 2];
        float g0 = 1.f/(1.f + __expf(-c0));
        float g1 = 1.f/(1.f + __expf(-c1));
        float g2 = 1.f/(1.f + __expf(-c2));
        float tot = g0 + g1 + g2 + 1e-6f;
        float push = g0/tot, pop = g1/tot, stay = g2/tot;
        alpha *= (1.f - push);
        float prev = __shfl_sync(0xffffffffu, p, (s + 15) & 15, 16);
        float nxt  = __shfl_sync(0xffffffffu, p, (s + 1) & 15, 16);
        p = push*prev + pop*nxt + stay*p;
        g_ptrs[((size_t)b*TT + t)*16 + s] = p;
        if (s == 0) g_alpha[b*TT + t] = alpha;
    }
}

// ---------------- HMMA split-bf16 GEMM with fused beta recurrence ---------------
#define ASTRIDE 136            // halves per row (272B: ldmatrix 8-row groups conflict-free)
#define SM_AHI 0
#define SM_ALO (128*ASTRIDE*2)       // 34816
#define SM_B   (2*128*ASTRIDE*2)     // 69632
#define SM_TOTAL (3*128*ASTRIDE*2)   // 104448 bytes

__device__ __forceinline__ void mma16816(float* d, const uint32_t* a, const uint32_t* b) {
    asm volatile(
        "mma.sync.aligned.m16n8k16.row.col.f32.bf16.bf16.f32 "
        "{%0,%1,%2,%3},{%4,%5,%6,%7},{%8,%9},{%0,%1,%2,%3};"
        : "+f"(d[0]), "+f"(d[1]), "+f"(d[2]), "+f"(d[3])
        : "r"(a[0]), "r"(a[1]), "r"(a[2]), "r"(a[3]), "r"(b[0]), "r"(b[1]));
}

__global__ __launch_bounds__(256, 2) void gemm_kernel(const float* __restrict__ mem0,
                                                      const float* __restrict__ zr,
                                                      const float* __restrict__ zi,
                                                      const float* __restrict__ ctrl) {
    extern __shared__ char smem[];
    __shared__ float sPush[128];
    unsigned short* sAhi = (unsigned short*)(smem + SM_AHI);
    unsigned short* sAlo = (unsigned short*)(smem + SM_ALO);
    unsigned short* sB   = (unsigned short*)(smem + SM_B);

    const int tid = threadIdx.x;
    const int lane = tid & 31;
    const int wid = tid >> 5;
    const int gid = lane >> 2;       // 0..7
    const int tig = lane & 3;        // 0..3
    const int wr = wid & 3;          // warp row group (4 x 32 rows)
    const int wc = wid >> 2;         // warp col group (2 x 64 cols)

    const bool is_beta = (blockIdx.x < NB_BLOCKS);

    float* C;
    int ncb, cstride;

    if (is_beta) {
        const int b0 = blockIdx.x * 4;     // 4 batches per block
        C = g_qkvb + (size_t)blockIdx.x * 128 * 256;
        ncb = 2; cstride = 256;

        if (tid < 128) {
            int bl = tid >> 5, t = tid & 31;
            const float* cp = ctrl + ((size_t)(b0 + bl)*TT + t)*3;
            float g0 = 1.f/(1.f + __expf(-cp[0]));
            float g1 = 1.f/(1.f + __expf(-cp[1]));
            float g2 = 1.f/(1.f + __expf(-cp[2]));
            sPush[tid] = g0 / (g0 + g1 + g2 + 1e-6f);
        }
        __syncthreads();

        {
            const int bl = tid >> 6, dd = tid & 63;
            const float* zrb = zr + (size_t)(b0 + bl)*2048 + dd;
            const float* zib = zi + (size_t)(b0 + bl)*2048 + dd;
            const float* pushp = &sPush[bl*32];
            const int f = dd & 31;
            float bL = 0.f, bH = 0.f;
            #pragma unroll 4
            for (int t = 0; t < TT; ++t) {
                float cs = g_ropeC[t*32 + f];
                float sn = g_ropeS[t*32 + f];
                float a = zrb[t*64], zb = zib[t*64];
                float vL = a*cs - zb*sn;
                float vH = a*sn + zb*cs;
                float push = pushp[t];
                bL = (1.f - push)*bL + push*vL;
                bH = (1.f - push)*bH + push*vH;
                int r = bl*32 + t;
                __nv_bfloat16 h = __float2bfloat16(bL);
                sAhi[r*ASTRIDE + dd] = __bfloat16_as_ushort(h);
                sAlo[r*ASTRIDE + dd] =
                    __bfloat16_as_ushort(__float2bfloat16(bL - __bfloat162float(h)));
                h = __float2bfloat16(bH);
                sAhi[r*ASTRIDE + dd + 64] = __bfloat16_as_ushort(h);
                sAlo[r*ASTRIDE + dd + 64] =
                    __bfloat16_as_ushort(__float2bfloat16(bH - __bfloat162float(h)));
            }
            g_betaT[(size_t)(b0 + bl)*128 + dd] = bL;
            g_betaT[(size_t)(b0 + bl)*128 + dd + 64] = bH;
        }
    } else {
        const size_t row0 = (size_t)(blockIdx.x - NB_BLOCKS) * 128;
        C = g_qkv0 + row0*384;
        ncb = 3; cstride = 384;
        const float* Ab = mem0 + row0*128;
        #pragma unroll
        for (int it = 0; it < 16; ++it) {
            int i = tid + it*256;                 // 0..4095
            int r = i >> 5, k = (i & 31) * 4;
            float4 v = *(const float4*)(Ab + (size_t)r*128 + k);
            __nv_bfloat16 h0 = __float2bfloat16(v.x);
            __nv_bfloat16 h1 = __float2bfloat16(v.y);
            __nv_bfloat16 h2 = __float2bfloat16(v.z);
            __nv_bfloat16 h3 = __float2bfloat16(v.w);
            __nv_bfloat16 l0 = __float2bfloat16(v.x - __bfloat162float(h0));
            __nv_bfloat16 l1 = __float2bfloat16(v.y - __bfloat162float(h1));
            __nv_bfloat16 l2 = __float2bfloat16(v.z - __bfloat162float(h2));
            __nv_bfloat16 l3 = __float2bfloat16(v.w - __bfloat162float(h3));
            uint64_t hv = (uint64_t)__bfloat16_as_ushort(h0)
                        | ((uint64_t)__bfloat16_as_ushort(h1) << 16)
                        | ((uint64_t)__bfloat16_as_ushort(h2) << 32)
                        | ((uint64_t)__bfloat16_as_ushort(h3) << 48);
            uint64_t lv = (uint64_t)__bfloat16_as_ushort(l0)
                        | ((uint64_t)__bfloat16_as_ushort(l1) << 16)
                        | ((uint64_t)__bfloat16_as_ushort(l2) << 32)
                        | ((uint64_t)__bfloat16_as_ushort(l3) << 48);
            *(uint64_t*)&sAhi[r*ASTRIDE + k] = hv;
            *(uint64_t*)&sAlo[r*ASTRIDE + k] = lv;
        }
    }

    // ldmatrix lane addressing
    const int lr = lane & 7;
    // A tile (16x16) at (r0 = wr*32 + m*16, k0): lane -> row r0+((lane>>3)&1)*8+lr,
    // col k0 + (lane>>4)*8.  Register order matches {a0,a1,a2,a3} of m16n8k16.
    const uint32_t aoff = ((uint32_t)(wr*32 + ((lane >> 3) & 1)*8 + lr)*ASTRIDE
                          + (lane >> 4)*8) * 2;
    const uint32_t aHiA0 = smem_u32(sAhi) + aoff;
    const uint32_t aHiA1 = aHiA0 + 16*ASTRIDE*2;
    const uint32_t aLoA0 = smem_u32(sAlo) + aoff;
    const uint32_t aLoA1 = aLoA0 + 16*ASTRIDE*2;
    // B pair p (j=2p,2p+1): lane -> row (wc*64 + p*16 + (lane>>4)*8 + lr),
    // col ((lane>>3)&1)*8.  Regs {j0.b0, j0.b1, j1.b0, j1.b1}.
    const uint32_t bA = smem_u32(sB)
        + ((uint32_t)(wc*64 + (lane >> 4)*8 + lr)*ASTRIDE + ((lane >> 3) & 1)*8) * 2;

    for (int cb = 0; cb < ncb; ++cb) {
        const int col0 = cb * 128;
        const int wr0 = is_beta ? (cb == 0 ? 0 : 256) : cb*128;   // W^T row offset

        float acc[2][8][4];
        #pragma unroll
        for (int m = 0; m < 2; ++m)
            #pragma unroll
            for (int j = 0; j < 8; ++j)
                #pragma unroll
                for (int q = 0; q < 4; ++q) acc[m][j][q] = 0.f;

        // -------- phase 1: B = Whi; acc += Ahi@Bhi + Alo@Bhi --------
        __syncthreads();
        #pragma unroll
        for (int it = 0; it < 8; ++it) {
            int i = tid + it*256;
            int r = i >> 4, k = (i & 15) * 8;
            *(uint4*)&sB[r*ASTRIDE + k] = *(const uint4*)(g_Wt_hi + (size_t)(wr0 + r)*128 + k);
        }
        __syncthreads();

        #pragma unroll
        for (int kk = 0; kk < 8; ++kk) {
            const uint32_t koff = kk*32;
            uint32_t ah0[4], ah1[4], al0[4], al1[4];
            LDSM4(ah0, aHiA0 + koff);
            LDSM4(ah1, aHiA1 + koff);
            LDSM4(al0, aLoA0 + koff);
            LDSM4(al1, aLoA1 + koff);
            #pragma unroll
            for (int p = 0; p < 4; ++p) {
                uint32_t bq[4];
                LDSM4(bq, bA + (uint32_t)p*(16*ASTRIDE*2) + koff);
                mma16816(acc[0][2*p],   ah0, bq);
                mma16816(acc[1][2*p],   ah1, bq);
                mma16816(acc[0][2*p],   al0, bq);
                mma16816(acc[1][2*p],   al1, bq);
                mma16816(acc[0][2*p+1], ah0, bq + 2);
                mma16816(acc[1][2*p+1], ah1, bq + 2);
                mma16816(acc[0][2*p+1], al0, bq + 2);
                mma16816(acc[1][2*p+1], al1, bq + 2);
            }
        }

        // -------- phase 2: B = Wlo; acc += Ahi@Blo --------
        __syncthreads();
        #pragma unroll
        for (int it = 0; it < 8; ++it) {
            int i = tid + it*256;
            int r = i >> 4, k = (i & 15) * 8;
            *(uint4*)&sB[r*ASTRIDE + k] = *(const uint4*)(g_Wt_lo + (size_t)(wr0 + r)*128 + k);
        }
        __syncthreads();

        #pragma unroll
        for (int kk = 0; kk < 8; ++kk) {
            const uint32_t koff = kk*32;
            uint32_t ah0[4], ah1[4];
            LDSM4(ah0, aHiA0 + koff);
            LDSM4(ah1, aHiA1 + koff);
            #pragma unroll
            for (int p = 0; p < 4; ++p) {
                uint32_t bq[4];
                LDSM4(bq, bA + (uint32_t)p*(16*ASTRIDE*2) + koff);
                mma16816(acc[0][2*p],   ah0, bq);
                mma16816(acc[1][2*p],   ah1, bq);
                mma16816(acc[0][2*p+1], ah0, bq + 2);
                mma16816(acc[1][2*p+1], ah1, bq + 2);
            }
        }

        // ---- epilogue: direct gmem stores (local rows) ----
        #pragma unroll
        for (int m = 0; m < 2; ++m) {
            int r = wr*32 + m*16 + gid;
            #pragma unroll
            for (int j = 0; j < 8; ++j) {
                int c = col0 + wc*64 + j*8 + 2*tig;
                *(float2*)(C + (size_t)r*cstride + c)     = make_float2(acc[m][j][0], acc[m][j][1]);
                *(float2*)(C + (size_t)(r+8)*cstride + c) = make_float2(acc[m][j][2], acc[m][j][3]);
            }
        }
    }
}

// ---------------- per-batch scan: warp-autonomous, 4 t per warp ----------------
#define ST 388   // padded slot stride (floats) for sM0

__global__ __launch_bounds__(256) void scan_kernel(const float* __restrict__ mem0,
                                                   float* __restrict__ out) {
    const int b = blockIdx.x;
    const int tid = threadIdx.x;
    const int wid = tid >> 5;
    const int lane = tid & 31;

    __shared__ __align__(16) float sM0[16*ST];   // per-slot: q0f|k0f|v0f
    __shared__ float sG0[16*17];                 // G0[s][j]
    __shared__ float sPA[8][16*17];              // per-warp ptr*attn tile
    __shared__ __align__(16) float sQw[8][128];  // per-warp qbeta
    __shared__ float sW[8][16];                  // per-warp w[j]
    __shared__ float sCj[8][16];                 // per-warp c[j]
    __shared__ float sPtrAll[512];               // ptr for all 32 t
    __shared__ float sAlphaAll[32];

    const float* base0 = g_qkv0 + (size_t)b*6144;
    for (int i = tid; i < 6144; i += 256)
        sM0[(i/384)*ST + (i % 384)] = base0[i];
    {
        const float* pb = g_ptrs + (size_t)b*512;
        for (int i = tid; i < 512; i += 256) sPtrAll[i] = pb[i];
        if (tid < 32) sAlphaAll[tid] = g_alpha[(size_t)b*32 + tid];
    }
    __syncthreads();

    // G0[s][j] = qf0[s] . kf0[j]
    {
        int s = tid >> 4, j = tid & 15;
        const float* q = &sM0[s*ST];
        const float* k = &sM0[j*ST + 128];
        float acc = 0.f;
        #pragma unroll 8
        for (int d = 0; d < 128; ++d) acc += q[d]*k[d];
        sG0[s*17 + j] = acc;
    }
    __syncthreads();

    const int s = lane >> 1, h = lane & 1;
    float* paw = sPA[wid];

    for (int it = 0; it < 4; ++it) {
        const int t = wid + it*8;
        const float* bb = g_qkvb + ((size_t)b*TT + t)*256;
        const float4 q4 = *(const float4*)(bb + lane*4);
        const float4 v4b = *(const float4*)(bb + 128 + lane*4);
        *(float4*)&sQw[wid][lane*4] = q4;
        __syncwarp();

        // w[j] = qbeta . kf0[j] — 2 lanes per j (halves), 1 shfl
        {
            const float* qp = &sQw[wid][h*64];
            const float* kp = &sM0[s*ST + 128 + h*64];
            float acc = 0.f;
            #pragma unroll
            for (int i = 0; i < 16; ++i) {
                const float4 qq = *(const float4*)(qp + i*4);
                const float4 kk = *(const float4*)(kp + i*4);
                acc += qq.x*kk.x + qq.y*kk.y + qq.z*kk.z + qq.w*kk.w;
            }
            acc += __shfl_xor_sync(0xffffffffu, acc, 1);
            if (h == 0) sW[wid][s] = acc;
        }
        __syncwarp();

        const float a = sAlphaAll[t];
        const float a2 = a*a;
        const float ptr_s = sPtrAll[t*16 + s];

        // softmax row s (2 lanes: 8 j each); row-constant terms dropped (exact)
        float L[8], m = -1e30f;
        #pragma unroll
        for (int i = 0; i < 8; ++i) {
            int j = h*8 + i;
            L[i] = 0.125f*(a2*sG0[s*17 + j] + a*sW[wid][j]);
            m = fmaxf(m, L[i]);
        }
        m = fmaxf(m, __shfl_xor_sync(0xffffffffu, m, 1));
        float sum = 0.f;
        #pragma unroll
        for (int i = 0; i < 8; ++i) { L[i] = __expf(L[i] - m); sum += L[i]; }
        sum += __shfl_xor_sync(0xffffffffu, sum, 1);
        const float pscl = ptr_s / sum;
        #pragma unroll
        for (int i = 0; i < 8; ++i) paw[s*17 + h*8 + i] = pscl*L[i];
        __syncwarp();

        // c[j] = sum_s pa[s][j]  (2 lanes per j: 8 s each)
        {
            int jc = lane >> 1, s0 = (lane & 1)*8;
            float cacc = 0.f;
            #pragma unroll
            for (int ss = 0; ss < 8; ++ss) cacc += paw[(s0 + ss)*17 + jc];
            cacc += __shfl_xor_sync(0xffffffffu, cacc, 1);
            if (h == 0) sCj[wid][jc] = cacc;
        }
        __syncwarp();

        // read[d] = a * sum_j c[j]*v0f[j][d] + csum * vbeta[d]
        float4 r = make_float4(0.f, 0.f, 0.f, 0.f);
        float csum = 0.f;
        #pragma unroll
        for (int j = 0; j < 16; ++j) {
            float cj = sCj[wid][j];
            const float4 vv = *(const float4*)&sM0[j*ST + 256 + lane*4];
            r.x += cj*vv.x; r.y += cj*vv.y; r.z += cj*vv.z; r.w += cj*vv.w;
            csum += cj;
        }
        float4 o;
        o.x = a*r.x + csum*v4b.x;
        o.y = a*r.y + csum*v4b.y;
        o.z = a*r.z + csum*v4b.z;
        o.w = a*r.w + csum*v4b.w;
        *(float4*)(out + ((size_t)t*BATCH + b)*128 + lane*4) = o;
        __syncwarp();   // pa/c consumed before next iteration overwrites
    }

    // epilogue: mem_f = alpha_T*mem0 + beta_T ; ptr_f ; active count
    __syncthreads();
    if (tid < 128) sG0[tid] = g_betaT[(size_t)b*128 + tid];
    __syncthreads();

    const float alphaT = sAlphaAll[31];
    float* out_mem = out + (size_t)TT*BATCH*128;
    const float* m0 = mem0 + (size_t)b*2048;
    for (int i = tid; i < 2048; i += 256)
        out_mem[(size_t)b*2048 + i] = alphaT*m0[i] + sG0[i & 127];

    float* out_ptr = out + (size_t)TT*BATCH*128 + (size_t)BATCH*2048;
    if (tid < 16) {
        float pv = sPtrAll[31*16 + tid];
        out_ptr[(size_t)b*16 + tid] = pv;
        int cnt = (pv > 0.1f) ? 1 : 0;
        cnt += __shfl_xor_sync(0x0000ffffu, cnt, 8, 16);
        cnt += __shfl_xor_sync(0x0000ffffu, cnt, 4, 16);
        cnt += __shfl_xor_sync(0x0000ffffu, cnt, 2, 16);
        cnt += __shfl_xor_sync(0x0000ffffu, cnt, 1, 16);
        if (tid == 0) atomicAdd(&g_active, cnt);
    }
}

__global__ void finalize_kernel(float* __restrict__ out) {
    out[(size_t)TT*BATCH*128 + (size_t)BATCH*2048 + (size_t)BATCH*16] =
        (float)g_active / (float)BATCH;
}

// ---------------- launcher ----------------------------------------------------
extern "C" void kernel_launch(void* const* d_in, const int* in_sizes, int n_in,
                              void* d_out, int out_size) {
    const float* zr   = (const float*)d_in[0];
    const float* zi   = (const float*)d_in[1];
    const float* ctrl = (const float*)d_in[2];
    const float* mem0 = (const float*)d_in[3];
    const float* ptr0 = (const float*)d_in[4];
    const float* Wqr  = (const float*)d_in[5];
    const float* Wqi  = (const float*)d_in[6];
    const float* Wkr  = (const float*)d_in[7];
    const float* Wki  = (const float*)d_in[8];
    const float* Wvr  = (const float*)d_in[9];
    const float* Wvi  = (const float*)d_in[10];
    float* out = (float*)d_out;

    cudaFuncSetAttribute(gemm_kernel, cudaFuncAttributeMaxDynamicSharedMemorySize, SM_TOTAL);

    build_wt_kernel<<<192, 256>>>(Wqr, Wqi, Wkr, Wki, Wvr, Wvi);
    rope_kernel<<<4, 256>>>();
    reset_kernel<<<1, 1>>>();
    ptr_alpha_kernel<<<BATCH/16, 256>>>(ctrl, ptr0);

    gemm_kernel<<<NB_BLOCKS + N0_BLOCKS, 256, SM_TOTAL>>>(mem0, zr, zi, ctrl);

    scan_kernel<<<BATCH, 256>>>(mem0, out);
    finalize_kernel<<<1, 1>>>(out);
}

// round 12
// speedup vs baseline: 1.1167x; 1.1167x over previous
#include <cuda_runtime.h>
#include <cuda_bf16.h>
#include <math.h>
#include <stdint.h>

#define BATCH 16384
#define TT 32
#define SS 16
#define NROWS_B (BATCH*TT)   // 524288
#define NROWS_0 (BATCH*SS)   // 262144
#define NB_BLOCKS (NROWS_B/128)  // 4096
#define N0_BLOCKS (NROWS_0/128)  // 2048

// ---------------- scratch (device globals; no allocations allowed) -------------
__device__ float g_qkvb[(size_t)NROWS_B*256];   // q(128)|v(128) of clin(beta)
__device__ float g_qkv0[(size_t)NROWS_0*384];   // clin(mem0): q|k|v
__device__ float g_alpha[NROWS_B];
__device__ float g_ptrs[(size_t)NROWS_B*16];
__device__ float g_betaT[(size_t)BATCH*128];    // beta at t=31 (for mem_f)
__device__ unsigned short g_Wt_hi[384*128];     // W^T split hi (bf16 bits): row n, col d
__device__ unsigned short g_Wt_lo[384*128];
__device__ float g_ropeC[1024], g_ropeS[1024];  // [t][f] rope tables
__device__ int   g_active;

__device__ __forceinline__ uint32_t smem_u32(const void* p) {
    uint32_t a;
    asm("{ .reg .u64 t; cvta.to.shared.u64 t, %1; cvt.u32.u64 %0, t; }" : "=r"(a) : "l"(p));
    return a;
}

#define LDSM4(r, a) \
    asm volatile("ldmatrix.sync.aligned.m8n8.x4.shared.b16 {%0,%1,%2,%3}, [%4];" \
        : "=r"((r)[0]), "=r"((r)[1]), "=r"((r)[2]), "=r"((r)[3]) : "r"(a))

// ---------------- build combined transposed/split weight -----------------------
__global__ void build_wt_kernel(const float* __restrict__ Wqr, const float* __restrict__ Wqi,
                                const float* __restrict__ Wkr, const float* __restrict__ Wki,
                                const float* __restrict__ Wvr, const float* __restrict__ Wvi) {
    int idx = blockIdx.x * blockDim.x + threadIdx.x;
    if (idx >= 384*128) return;
    int n = idx / 128, d = idx % 128;          // n = output col, d = input dim
    int grp = n >> 7, cc = n & 127, e = cc & 63, im = cc >> 6;
    const float* Wr = (grp == 0) ? Wqr : (grp == 1) ? Wkr : Wvr;
    const float* Wi = (grp == 0) ? Wqi : (grp == 1) ? Wki : Wvi;
    int dr = d & 63;
    float v;
    if (im == 0) v = (d < 64) ? Wr[e*64 + dr] : -Wi[e*64 + dr];
    else         v = (d < 64) ? Wi[e*64 + dr] :  Wr[e*64 + dr];
    __nv_bfloat16 h = __float2bfloat16(v);
    float lo = v - __bfloat162float(h);
    __nv_bfloat16 l = __float2bfloat16(lo);
    g_Wt_hi[idx] = __bfloat16_as_ushort(h);
    g_Wt_lo[idx] = __bfloat16_as_ushort(l);
}

__global__ void rope_kernel() {
    int idx = blockIdx.x * blockDim.x + threadIdx.x;
    if (idx >= 1024) return;
    int t = idx >> 5, f = idx & 31;
    double freq = pow(10000.0, -((double)(2*f)) / 64.0);
    float ang = (float)((double)t * freq);
    g_ropeC[idx] = cosf(ang);
    g_ropeS[idx] = sinf(ang);
}

__global__ void reset_kernel() { g_active = 0; }

// ---------------- slim prep: alpha + ptr recurrences (16 lanes / batch) --------
__global__ __launch_bounds__(256) void ptr_alpha_kernel(const float* __restrict__ ctrl,
                                                        const float* __restrict__ ptr0) {
    const int grp = threadIdx.x >> 4;          // 0..15: batch within block
    const int s = threadIdx.x & 15;
    const int b = blockIdx.x*16 + grp;
    float p = ptr0[b*16 + s];
    float alpha = 1.f;
    const float* cb = ctrl + (size_t)b*96;
    for (int t = 0; t < TT; ++t) {
        float c0 = cb[t*3 + 0], c1 = cb[t*3 + 1], c2 = cb[t*3 + 2];
        float g0 = 1.f/(1.f + __expf(-c0));
        float g1 = 1.f/(1.f + __expf(-c1));
        float g2 = 1.f/(1.f + __expf(-c2));
        float tot = g0 + g1 + g2 + 1e-6f;
        float push = g0/tot, pop = g1/tot, stay = g2/tot;
        alpha *= (1.f - push);
        float prev = __shfl_sync(0xffffffffu, p, (s + 15) & 15, 16);
        float nxt  = __shfl_sync(0xffffffffu, p, (s + 1) & 15, 16);
        p = push*prev + pop*nxt + stay*p;
        g_ptrs[((size_t)b*TT + t)*16 + s] = p;
        if (s == 0) g_alpha[b*TT + t] = alpha;
    }
}

// ---------------- HMMA split-bf16 GEMM with fused beta recurrence ---------------
#define ASTRIDE 136            // halves per row (272B: ldmatrix 8-row groups conflict-free)
#define SM_AHI 0
#define SM_ALO (128*ASTRIDE*2)       // 34816
#define SM_B   (2*128*ASTRIDE*2)     // 69632
#define SM_TOTAL (3*128*ASTRIDE*2)   // 104448 bytes

__device__ __forceinline__ void mma16816(float* d, const uint32_t* a, const uint32_t* b) {
    asm volatile(
        "mma.sync.aligned.m16n8k16.row.col.f32.bf16.bf16.f32 "
        "{%0,%1,%2,%3},{%4,%5,%6,%7},{%8,%9},{%0,%1,%2,%3};"
        : "+f"(d[0]), "+f"(d[1]), "+f"(d[2]), "+f"(d[3])
        : "r"(a[0]), "r"(a[1]), "r"(a[2]), "r"(a[3]), "r"(b[0]), "r"(b[1]));
}

__global__ __launch_bounds__(256, 2) void gemm_kernel(const float* __restrict__ mem0,
                                                      const float* __restrict__ zr,
                                                      const float* __restrict__ zi,
                                                      const float* __restrict__ ctrl) {
    extern __shared__ char smem[];
    __shared__ float sPush[128];
    unsigned short* sAhi = (unsigned short*)(smem + SM_AHI);
    unsigned short* sAlo = (unsigned short*)(smem + SM_ALO);
    unsigned short* sB   = (unsigned short*)(smem + SM_B);

    const int tid = threadIdx.x;
    const int lane = tid & 31;
    const int wid = tid >> 5;
    const int gid = lane >> 2;       // 0..7
    const int tig = lane & 3;        // 0..3
    const int wr = wid & 3;          // warp row group (4 x 32 rows)
    const int wc = wid >> 2;         // warp col group (2 x 64 cols)

    const bool is_beta = (blockIdx.x < NB_BLOCKS);

    float* C;
    int ncb, cstride;

    if (is_beta) {
        const int b0 = blockIdx.x * 4;     // 4 batches per block
        C = g_qkvb + (size_t)blockIdx.x * 128 * 256;
        ncb = 2; cstride = 256;

        if (tid < 128) {
            int bl = tid >> 5, t = tid & 31;
            const float* cp = ctrl + ((size_t)(b0 + bl)*TT + t)*3;
            float g0 = 1.f/(1.f + __expf(-cp[0]));
            float g1 = 1.f/(1.f + __expf(-cp[1]));
            float g2 = 1.f/(1.f + __expf(-cp[2]));
            sPush[tid] = g0 / (g0 + g1 + g2 + 1e-6f);
        }
        __syncthreads();

        {
            const int bl = tid >> 6, dd = tid & 63;
            const float* zrb = zr + (size_t)(b0 + bl)*2048 + dd;
            const float* zib = zi + (size_t)(b0 + bl)*2048 + dd;
            const float* pushp = &sPush[bl*32];
            const int f = dd & 31;
            float bL = 0.f, bH = 0.f;
            #pragma unroll 4
            for (int t = 0; t < TT; ++t) {
                float cs = g_ropeC[t*32 + f];
                float sn = g_ropeS[t*32 + f];
                float a = zrb[t*64], zb = zib[t*64];
                float vL = a*cs - zb*sn;
                float vH = a*sn + zb*cs;
                float push = pushp[t];
                bL = (1.f - push)*bL + push*vL;
                bH = (1.f - push)*bH + push*vH;
                int r = bl*32 + t;
                __nv_bfloat16 h = __float2bfloat16(bL);
                sAhi[r*ASTRIDE + dd] = __bfloat16_as_ushort(h);
                sAlo[r*ASTRIDE + dd] =
                    __bfloat16_as_ushort(__float2bfloat16(bL - __bfloat162float(h)));
                h = __float2bfloat16(bH);
                sAhi[r*ASTRIDE + dd + 64] = __bfloat16_as_ushort(h);
                sAlo[r*ASTRIDE + dd + 64] =
                    __bfloat16_as_ushort(__float2bfloat16(bH - __bfloat162float(h)));
            }
            g_betaT[(size_t)(b0 + bl)*128 + dd] = bL;
            g_betaT[(size_t)(b0 + bl)*128 + dd + 64] = bH;
        }
    } else {
        const size_t row0 = (size_t)(blockIdx.x - NB_BLOCKS) * 128;
        C = g_qkv0 + row0*384;
        ncb = 3; cstride = 384;
        const float* Ab = mem0 + row0*128;
        #pragma unroll
        for (int it = 0; it < 16; ++it) {
            int i = tid + it*256;                 // 0..4095
            int r = i >> 5, k = (i & 31) * 4;
            float4 v = *(const float4*)(Ab + (size_t)r*128 + k);
            __nv_bfloat16 h0 = __float2bfloat16(v.x);
            __nv_bfloat16 h1 = __float2bfloat16(v.y);
            __nv_bfloat16 h2 = __float2bfloat16(v.z);
            __nv_bfloat16 h3 = __float2bfloat16(v.w);
            __nv_bfloat16 l0 = __float2bfloat16(v.x - __bfloat162float(h0));
            __nv_bfloat16 l1 = __float2bfloat16(v.y - __bfloat162float(h1));
            __nv_bfloat16 l2 = __float2bfloat16(v.z - __bfloat162float(h2));
            __nv_bfloat16 l3 = __float2bfloat16(v.w - __bfloat162float(h3));
            uint64_t hv = (uint64_t)__bfloat16_as_ushort(h0)
                        | ((uint64_t)__bfloat16_as_ushort(h1) << 16)
                        | ((uint64_t)__bfloat16_as_ushort(h2) << 32)
                        | ((uint64_t)__bfloat16_as_ushort(h3) << 48);
            uint64_t lv = (uint64_t)__bfloat16_as_ushort(l0)
                        | ((uint64_t)__bfloat16_as_ushort(l1) << 16)
                        | ((uint64_t)__bfloat16_as_ushort(l2) << 32)
                        | ((uint64_t)__bfloat16_as_ushort(l3) << 48);
            *(uint64_t*)&sAhi[r*ASTRIDE + k] = hv;
            *(uint64_t*)&sAlo[r*ASTRIDE + k] = lv;
        }
    }

    // ldmatrix lane addressing
    const int lr = lane & 7;
    const uint32_t aoff = ((uint32_t)(wr*32 + ((lane >> 3) & 1)*8 + lr)*ASTRIDE
                          + (lane >> 4)*8) * 2;
    const uint32_t aHiA0 = smem_u32(sAhi) + aoff;
    const uint32_t aHiA1 = aHiA0 + 16*ASTRIDE*2;
    const uint32_t aLoA0 = smem_u32(sAlo) + aoff;
    const uint32_t aLoA1 = aLoA0 + 16*ASTRIDE*2;
    const uint32_t bA = smem_u32(sB)
        + ((uint32_t)(wc*64 + (lane >> 4)*8 + lr)*ASTRIDE + ((lane >> 3) & 1)*8) * 2;

    for (int cb = 0; cb < ncb; ++cb) {
        const int col0 = cb * 128;
        const int wr0 = is_beta ? (cb == 0 ? 0 : 256) : cb*128;   // W^T row offset

        float acc[2][8][4];
        #pragma unroll
        for (int m = 0; m < 2; ++m)
            #pragma unroll
            for (int j = 0; j < 8; ++j)
                #pragma unroll
                for (int q = 0; q < 4; ++q) acc[m][j][q] = 0.f;

        // -------- phase 1: B = Whi; acc += Ahi@Bhi + Alo@Bhi --------
        __syncthreads();
        #pragma unroll
        for (int it = 0; it < 8; ++it) {
            int i = tid + it*256;
            int r = i >> 4, k = (i & 15) * 8;
            *(uint4*)&sB[r*ASTRIDE + k] = *(const uint4*)(g_Wt_hi + (size_t)(wr0 + r)*128 + k);
        }
        __syncthreads();

        #pragma unroll
        for (int kk = 0; kk < 8; ++kk) {
            const uint32_t koff = kk*32;
            uint32_t ah0[4], ah1[4], al0[4], al1[4];
            LDSM4(ah0, aHiA0 + koff);
            LDSM4(ah1, aHiA1 + koff);
            LDSM4(al0, aLoA0 + koff);
            LDSM4(al1, aLoA1 + koff);
            #pragma unroll
            for (int p = 0; p < 4; ++p) {
                uint32_t bq[4];
                LDSM4(bq, bA + (uint32_t)p*(16*ASTRIDE*2) + koff);
                mma16816(acc[0][2*p],   ah0, bq);
                mma16816(acc[1][2*p],   ah1, bq);
                mma16816(acc[0][2*p],   al0, bq);
                mma16816(acc[1][2*p],   al1, bq);
                mma16816(acc[0][2*p+1], ah0, bq + 2);
                mma16816(acc[1][2*p+1], ah1, bq + 2);
                mma16816(acc[0][2*p+1], al0, bq + 2);
                mma16816(acc[1][2*p+1], al1, bq + 2);
            }
        }

        // -------- phase 2: B = Wlo; acc += Ahi@Blo --------
        __syncthreads();
        #pragma unroll
        for (int it = 0; it < 8; ++it) {
            int i = tid + it*256;
            int r = i >> 4, k = (i & 15) * 8;
            *(uint4*)&sB[r*ASTRIDE + k] = *(const uint4*)(g_Wt_lo + (size_t)(wr0 + r)*128 + k);
        }
        __syncthreads();

        #pragma unroll
        for (int kk = 0; kk < 8; ++kk) {
            const uint32_t koff = kk*32;
            uint32_t ah0[4], ah1[4];
            LDSM4(ah0, aHiA0 + koff);
            LDSM4(ah1, aHiA1 + koff);
            #pragma unroll
            for (int p = 0; p < 4; ++p) {
                uint32_t bq[4];
                LDSM4(bq, bA + (uint32_t)p*(16*ASTRIDE*2) + koff);
                mma16816(acc[0][2*p],   ah0, bq);
                mma16816(acc[1][2*p],   ah1, bq);
                mma16816(acc[0][2*p+1], ah0, bq + 2);
                mma16816(acc[1][2*p+1], ah1, bq + 2);
            }
        }

        // ---- epilogue: direct gmem stores (local rows) ----
        #pragma unroll
        for (int m = 0; m < 2; ++m) {
            int r = wr*32 + m*16 + gid;
            #pragma unroll
            for (int j = 0; j < 8; ++j) {
                int c = col0 + wc*64 + j*8 + 2*tig;
                *(float2*)(C + (size_t)r*cstride + c)     = make_float2(acc[m][j][0], acc[m][j][1]);
                *(float2*)(C + (size_t)(r+8)*cstride + c) = make_float2(acc[m][j][2], acc[m][j][3]);
            }
        }
    }
}

// ---------------- per-batch scan: warp-autonomous (round-8 pattern) ------------
#define ST 388   // padded slot stride (floats) for sM0

__global__ __launch_bounds__(256) void scan_kernel(const float* __restrict__ mem0,
                                                   float* __restrict__ out) {
    const int b = blockIdx.x;
    const int tid = threadIdx.x;
    const int wid = tid >> 5;
    const int lane = tid & 31;

    __shared__ __align__(16) float sM0[16*ST];   // per-slot: q0f|k0f|v0f
    __shared__ float sG0[16*17];                 // G0[s][j]
    __shared__ float sPA[8][16*17];              // per-warp ptr*attn tile
    __shared__ float sPtrAll[512];               // ptr for all 32 t
    __shared__ float sAlphaAll[32];

    const float* base0 = g_qkv0 + (size_t)b*6144;
    for (int i = tid; i < 6144; i += 256)
        sM0[(i/384)*ST + (i % 384)] = base0[i];
    {
        const float* pb = g_ptrs + (size_t)b*512;
        for (int i = tid; i < 512; i += 256) sPtrAll[i] = pb[i];
        if (tid < 32) sAlphaAll[tid] = g_alpha[(size_t)b*32 + tid];
    }
    __syncthreads();

    // G0[s][j] = qf0[s] . kf0[j]
    {
        int s = tid >> 4, j = tid & 15;
        const float* q = &sM0[s*ST];
        const float* k = &sM0[j*ST + 128];
        float acc = 0.f;
        #pragma unroll 8
        for (int d = 0; d < 128; ++d) acc += q[d]*k[d];
        sG0[s*17 + j] = acc;
    }
    __syncthreads();

    const int s = lane >> 1, h = lane & 1;
    float* paw = sPA[wid];

    for (int it = 0; it < 4; ++it) {
        const int t = wid + it*8;
        const float* bb = g_qkvb + ((size_t)b*TT + t)*256;
        const float4 q4 = *(const float4*)(bb + lane*4);
        const float4 v4b = *(const float4*)(bb + 128 + lane*4);

        // w[j] = qbeta . kf0[j] — broadcast-row butterfly; result on ALL lanes
        float wreg[16];
        #pragma unroll
        for (int j = 0; j < 16; ++j) {
            const float4 k4 = *(const float4*)&sM0[j*ST + 128 + lane*4];
            float p = q4.x*k4.x + q4.y*k4.y + q4.z*k4.z + q4.w*k4.w;
            p += __shfl_xor_sync(0xffffffffu, p, 16);
            p += __shfl_xor_sync(0xffffffffu, p, 8);
            p += __shfl_xor_sync(0xffffffffu, p, 4);
            p += __shfl_xor_sync(0xffffffffu, p, 2);
            p += __shfl_xor_sync(0xffffffffu, p, 1);
            wreg[j] = p;
        }

        const float a = sAlphaAll[t];
        const float a2 = a*a;
        const float ptr_s = sPtrAll[t*16 + s];

        // softmax row s (2 lanes: 8 j each); row-constant terms dropped (exact)
        float L[8], m = -1e30f;
        #pragma unroll
        for (int i = 0; i < 8; ++i) {
            int j = h*8 + i;
            L[i] = 0.125f*(a2*sG0[s*17 + j] + a*wreg[j]);
            m = fmaxf(m, L[i]);
        }
        m = fmaxf(m, __shfl_xor_sync(0xffffffffu, m, 1));
        float sum = 0.f;
        #pragma unroll
        for (int i = 0; i < 8; ++i) { L[i] = __expf(L[i] - m); sum += L[i]; }
        sum += __shfl_xor_sync(0xffffffffu, sum, 1);
        const float pscl = ptr_s / sum;
        #pragma unroll
        for (int i = 0; i < 8; ++i) paw[s*17 + h*8 + i] = pscl*L[i];
        __syncwarp();

        // c[j] = sum_s pa[s][j]  (2 lanes per j: 8 s each)
        float cacc = 0.f;
        {
            int jc = lane >> 1, s0 = (lane & 1)*8;
            #pragma unroll
            for (int ss = 0; ss < 8; ++ss) cacc += paw[(s0 + ss)*17 + jc];
            cacc += __shfl_xor_sync(0xffffffffu, cacc, 1);
        }
        __syncwarp();   // pa consumed before next iteration overwrites

        // read[d] = a * sum_j c[j]*v0f[j][d] + csum * vbeta[d]
        float4 r = make_float4(0.f, 0.f, 0.f, 0.f);
        float csum = 0.f;
        #pragma unroll
        for (int j = 0; j < 16; ++j) {
            float cj = __shfl_sync(0xffffffffu, cacc, j << 1);
            const float4 vv = *(const float4*)&sM0[j*ST + 256 + lane*4];
            r.x += cj*vv.x; r.y += cj*vv.y; r.z += cj*vv.z; r.w += cj*vv.w;
            csum += cj;
        }
        float4 o;
        o.x = a*r.x + csum*v4b.x;
        o.y = a*r.y + csum*v4b.y;
        o.z = a*r.z + csum*v4b.z;
        o.w = a*r.w + csum*v4b.w;
        *(float4*)(out + ((size_t)t*BATCH + b)*128 + lane*4) = o;
    }

    // epilogue: mem_f = alpha_T*mem0 + beta_T ; ptr_f ; active count
    __syncthreads();
    if (tid < 128) sG0[tid] = g_betaT[(size_t)b*128 + tid];
    __syncthreads();

    const float alphaT = sAlphaAll[31];
    float* out_mem = out + (size_t)TT*BATCH*128;
    const float* m0 = mem0 + (size_t)b*2048;
    for (int i = tid; i < 2048; i += 256)
        out_mem[(size_t)b*2048 + i] = alphaT*m0[i] + sG0[i & 127];

    float* out_ptr = out + (size_t)TT*BATCH*128 + (size_t)BATCH*2048;
    if (tid < 16) {
        float pv = sPtrAll[31*16 + tid];
        out_ptr[(size_t)b*16 + tid] = pv;
        int cnt = (pv > 0.1f) ? 1 : 0;
        cnt += __shfl_xor_sync(0x0000ffffu, cnt, 8, 16);
        cnt += __shfl_xor_sync(0x0000ffffu, cnt, 4, 16);
        cnt += __shfl_xor_sync(0x0000ffffu, cnt, 2, 16);
        cnt += __shfl_xor_sync(0x0000ffffu, cnt, 1, 16);
        if (tid == 0) atomicAdd(&g_active, cnt);
    }
}

__global__ void finalize_kernel(float* __restrict__ out) {
    out[(size_t)TT*BATCH*128 + (size_t)BATCH*2048 + (size_t)BATCH*16] =
        (float)g_active / (float)BATCH;
}

// ---------------- launcher ----------------------------------------------------
extern "C" void kernel_launch(void* const* d_in, const int* in_sizes, int n_in,
                              void* d_out, int out_size) {
    const float* zr   = (const float*)d_in[0];
    const float* zi   = (const float*)d_in[1];
    const float* ctrl = (const float*)d_in[2];
    const float* mem0 = (const float*)d_in[3];
    const float* ptr0 = (const float*)d_in[4];
    const float* Wqr  = (const float*)d_in[5];
    const float* Wqi  = (const float*)d_in[6];
    const float* Wkr  = (const float*)d_in[7];
    const float* Wki  = (const float*)d_in[8];
    const float* Wvr  = (const float*)d_in[9];
    const float* Wvi  = (const float*)d_in[10];
    float* out = (float*)d_out;

    cudaFuncSetAttribute(gemm_kernel, cudaFuncAttributeMaxDynamicSharedMemorySize, SM_TOTAL);

    build_wt_kernel<<<192, 256>>>(Wqr, Wqi, Wkr, Wki, Wvr, Wvi);
    rope_kernel<<<4, 256>>>();
    reset_kernel<<<1, 1>>>();
    ptr_alpha_kernel<<<BATCH/16, 256>>>(ctrl, ptr0);

    gemm_kernel<<<NB_BLOCKS + N0_BLOCKS, 256, SM_TOTAL>>>(mem0, zr, zi, ctrl);

    scan_kernel<<<BATCH, 256>>>(mem0, out);
    finalize_kernel<<<1, 1>>>(out);
}